// round 14
// baseline (speedup 1.0000x reference)
#include <cuda_runtime.h>

#define N_NODES 8192
#define NV4 (N_NODES / 4)       // 2048 float4 per row
#define PSI 64
#define GRID_RS 1184            // 148 SMs x 8 blocks, grid-stride over rows
#define PF_BLOCKS 256           // prefetch blocks inside the scatter kernel
#define PF_ROWS 768             // 24 MB warmed into L2 during the scatter phase

// __device__ scratch (no allocations allowed).
// g_agg zero-init at load; node_mlp reads-then-zeros it each replay.
__device__ float g_agg[N_NODES];
__device__ float g_t[N_NODES];
__device__ float g_s[N_NODES];
__device__ float g_sink;        // prefetch DCE guard (never actually written)

// ---------------------------------------------------------------------------
// Kernel 1: heterogeneous blocks.
//  - blocks [0, PF_BLOCKS): trigger PDL completion IMMEDIATELY, then stream
//    the first PF_ROWS rows of adj into L2 (fills the DRAM-idle window).
//    Because they trigger first, the downstream chain does NOT wait for them.
//  - blocks [PF_BLOCKS, ...): edge MLP + scatter-add (exit = implicit trigger).
// Edge MLP algebraic fast path (zero hidden bias, verified on device):
//   f(v) = v*Cp + b2  (v >= 0),   f(v) = v*Cn + b2  (v < 0).
// Generic 64-term fallback keeps it exact for arbitrary inputs.
// ---------------------------------------------------------------------------
__global__ __launch_bounds__(256) void k_scatter_prefetch(
        const float* __restrict__ adj,
        const int* __restrict__ col,
        const float* __restrict__ values,
        const float* __restrict__ w1,
        const float* __restrict__ b1,
        const float* __restrict__ w2,
        const float* __restrict__ b2,
        int nnz) {
    if (blockIdx.x < PF_BLOCKS) {
        cudaTriggerProgrammaticLaunchCompletion();   // release dependents now
        const float4* __restrict__ a = reinterpret_cast<const float4*>(adj);
        const int total = PF_ROWS * NV4;             // 1.5M float4
        float acc = 0.0f;
        for (int i = blockIdx.x * 256 + threadIdx.x; i < total;
             i += PF_BLOCKS * 256) {
            float4 v = __ldcg(&a[i]);                // L2-allocating load
            acc += v.x + v.y + v.z + v.w;
        }
        if (acc == -1.2345678e-33f) g_sink = acc;    // keep loads alive
        return;
    }

    __shared__ float sw1[PSI], sb1[PSI], sw2[PSI];
    __shared__ float sCp, sCn, sb2;
    __shared__ int sfast;
    if (threadIdx.x < PSI) {
        sw1[threadIdx.x] = w1[threadIdx.x];
        sb1[threadIdx.x] = b1[threadIdx.x];
        sw2[threadIdx.x] = w2[threadIdx.x];
    }
    if (threadIdx.x == 0) sb2 = b2[0];
    __syncthreads();
    if (threadIdx.x == 0) {
        float cp = 0.0f, cn = 0.0f;
        int ok = 1;
#pragma unroll
        for (int j = 0; j < PSI; j++) {
            float w = sw1[j];
            float p = w * sw2[j];
            if (w > 0.0f) cp += p;
            else if (w < 0.0f) cn += p;
            if (sb1[j] != 0.0f) ok = 0;
        }
        sCp = cp; sCn = cn; sfast = ok;
    }
    __syncthreads();

    int i = (blockIdx.x - PF_BLOCKS) * 256 + threadIdx.x;
    if (i >= nnz) return;
    float v = values[i];
    float feat;
    if (sfast) {
        feat = fmaf(v, (v >= 0.0f) ? sCp : sCn, sb2);
    } else {
        float p0 = 0.0f, p1 = 0.0f, p2 = 0.0f, p3 = 0.0f;
#pragma unroll
        for (int j = 0; j < PSI; j += 4) {
            p0 = fmaf(fmaxf(fmaf(v, sw1[j+0], sb1[j+0]), 0.0f), sw2[j+0], p0);
            p1 = fmaf(fmaxf(fmaf(v, sw1[j+1], sb1[j+1]), 0.0f), sw2[j+1], p1);
            p2 = fmaf(fmaxf(fmaf(v, sw1[j+2], sb1[j+2]), 0.0f), sw2[j+2], p2);
            p3 = fmaf(fmaxf(fmaf(v, sw1[j+3], sb1[j+3]), 0.0f), sw2[j+3], p3);
        }
        feat = sb2 + (p0 + p1) + (p2 + p3);
    }
    atomicAdd(&g_agg[col[i]], feat);
}

// ---------------------------------------------------------------------------
// Kernel 2: node MLP, store struct^2, re-zero g_agg for the next replay.
// PDL secondary (releases once scatter blocks exit + prefetch blocks trigger).
// ---------------------------------------------------------------------------
__global__ __launch_bounds__(512) void k_node_mlp(
        const float* __restrict__ w1,
        const float* __restrict__ b1,
        const float* __restrict__ w2,
        const float* __restrict__ b2) {
    __shared__ float sw1[PSI], sb1[PSI], sw2[PSI], sb2;
    if (threadIdx.x < PSI) {
        sw1[threadIdx.x] = w1[threadIdx.x];
        sb1[threadIdx.x] = b1[threadIdx.x];
        sw2[threadIdx.x] = w2[threadIdx.x];
    }
    if (threadIdx.x == 0) sb2 = b2[0];
    __syncthreads();

    cudaGridDependencySynchronize();   // all g_agg atomics visible

    int i = blockIdx.x * 512 + threadIdx.x;
    if (i >= N_NODES) return;
    float x = g_agg[i];
    g_agg[i] = 0.0f;              // reset for next graph replay
    float p0 = 0.0f, p1 = 0.0f, p2 = 0.0f, p3 = 0.0f;
#pragma unroll
    for (int j = 0; j < PSI; j += 4) {
        p0 = fmaf(fmaxf(fmaf(x, sw1[j+0], sb1[j+0]), 0.0f), sw2[j+0], p0);
        p1 = fmaf(fmaxf(fmaf(x, sw1[j+1], sb1[j+1]), 0.0f), sw2[j+1], p1);
        p2 = fmaf(fmaxf(fmaf(x, sw1[j+2], sb1[j+2]), 0.0f), sw2[j+2], p2);
        p3 = fmaf(fmaxf(fmaf(x, sw1[j+3], sb1[j+3]), 0.0f), sw2[j+3], p3);
    }
    float acc = sb2 + (p0 + p1) + (p2 + p3);
    g_t[i] = acc * acc;
}

// ---------------------------------------------------------------------------
// Kernel 3: row score.  s[r] = sum_n adj[r,n]^2 * t[n]
// R13's measured-best body: grid-stride rows, grid 1184 (8 blocks/SM),
// unroll-4 streaming with __ldcs, smem block reduction.  Rows 0..PF_ROWS-1
// hit the L2 lines warmed by the prefetch blocks.  PDL secondary.
// ---------------------------------------------------------------------------
__global__ __launch_bounds__(256, 8) void k_row_score(const float* __restrict__ adj) {
    __shared__ float warp_sum[8];
    const float4* __restrict__ tv = reinterpret_cast<const float4*>(g_t);

    cudaGridDependencySynchronize();   // g_t ready

    for (int row = blockIdx.x; row < N_NODES; row += GRID_RS) {
        const float4* __restrict__ a =
            reinterpret_cast<const float4*>(adj + (size_t)row * N_NODES);
        float acc = 0.0f;
#pragma unroll 4
        for (int i = threadIdx.x; i < NV4; i += 256) {
            float4 av = __ldcs(&a[i]);
            float4 tw = __ldg(&tv[i]);
            acc = fmaf(av.x * av.x, tw.x, acc);
            acc = fmaf(av.y * av.y, tw.y, acc);
            acc = fmaf(av.z * av.z, tw.z, acc);
            acc = fmaf(av.w * av.w, tw.w, acc);
        }
#pragma unroll
        for (int off = 16; off > 0; off >>= 1)
            acc += __shfl_down_sync(0xffffffffu, acc, off);
        if ((threadIdx.x & 31) == 0) warp_sum[threadIdx.x >> 5] = acc;
        __syncthreads();
        if (threadIdx.x < 8) {
            float v = warp_sum[threadIdx.x];
#pragma unroll
            for (int off = 4; off > 0; off >>= 1)
                v += __shfl_down_sync(0xffu, v, off);
            if (threadIdx.x == 0) g_s[row] = v;
        }
        __syncthreads();   // warp_sum reuse next row
    }
}

// ---------------------------------------------------------------------------
// Kernel 4: gather per-edge output (g_s is L2-hot).  PDL secondary.
// ---------------------------------------------------------------------------
__global__ __launch_bounds__(256) void k_gather(const int* __restrict__ src_nodes,
                                                float* __restrict__ out, int E) {
    int e = blockIdx.x * 256 + threadIdx.x;
    cudaGridDependencySynchronize();   // g_s ready
    if (e < E) out[e] = g_s[src_nodes[e]];
}

// ---------------------------------------------------------------------------
// launch helper: PDL launch (programmatic stream serialization)
// ---------------------------------------------------------------------------
template <typename... Args>
static inline void launch_pdl(void (*kern)(Args...), dim3 grid, dim3 block,
                              Args... args) {
    cudaLaunchAttribute attr[1];
    attr[0].id = cudaLaunchAttributeProgrammaticStreamSerialization;
    attr[0].val.programmaticStreamSerializationAllowed = 1;
    cudaLaunchConfig_t cfg{};
    cfg.gridDim = grid;
    cfg.blockDim = block;
    cfg.dynamicSmemBytes = 0;
    cfg.stream = 0;
    cfg.attrs = attr;
    cfg.numAttrs = 1;
    cudaLaunchKernelEx(&cfg, kern, args...);
}

// ---------------------------------------------------------------------------
// launch
// Inputs (metadata order): col, values, adj, src_nodes,
//                          w1e, b1e, w2e, b2e, w1n, b1n, w2n, b2n
// ---------------------------------------------------------------------------
extern "C" void kernel_launch(void* const* d_in, const int* in_sizes, int n_in,
                              void* d_out, int out_size) {
    const int*   col       = (const int*)d_in[0];
    const float* values    = (const float*)d_in[1];
    const float* adj       = (const float*)d_in[2];
    const int*   src_nodes = (const int*)d_in[3];
    const float* w1e = (const float*)d_in[4];
    const float* b1e = (const float*)d_in[5];
    const float* w2e = (const float*)d_in[6];
    const float* b2e = (const float*)d_in[7];
    const float* w1n = (const float*)d_in[8];
    const float* b1n = (const float*)d_in[9];
    const float* w2n = (const float*)d_in[10];
    const float* b2n = (const float*)d_in[11];
    float* out = (float*)d_out;

    const int nnz = in_sizes[0];   // 262144
    const int E   = in_sizes[3];   // 32768

    const int scatter_blocks = (nnz + 255) / 256;

    // primary: prefetch blocks + scatter blocks in one kernel
    k_scatter_prefetch<<<PF_BLOCKS + scatter_blocks, 256>>>(
        adj, col, values, w1e, b1e, w2e, b2e, nnz);

    // dependents: PDL with grid-sync
    launch_pdl(k_node_mlp, dim3((N_NODES + 511) / 512), dim3(512),
               w1n, b1n, w2n, b2n);
    launch_pdl(k_row_score, dim3(GRID_RS), dim3(256), adj);
    launch_pdl(k_gather, dim3((E + 255) / 256), dim3(256),
               src_nodes, out, E);
}